// round 7
// baseline (speedup 1.0000x reference)
#include <cuda_runtime.h>
#include <cstdint>
#include <math.h>

#define NODE_DIM_   128
#define NUM_IRREPS_ 224
#define SPH_DIM_    480
#define HIDDEN_     576
#define NUM_BASIS_  20
#define N_NODES_    30000
#define N_EDGES_    480000
#define EPB_        8
#define MAXD_       32
#define SCAN_BLKS_  118          // ceil(30000/256)

// Scratch (device globals)
__device__ float g_hidden[(size_t)N_NODES_ * NODE_DIM_];
__device__ float g_scalar_out[(size_t)N_NODES_ * HIDDEN_];
__device__ int   g_count[N_NODES_];
__device__ int   g_offs[N_NODES_];     // block-local exclusive (scan1)
__device__ int   g_cursor[N_NODES_];   // mutable copy for perm
__device__ int   g_part[128];          // per-scan-block totals -> exclusive
__device__ int   g_perm[N_EDGES_];

// ---------------- counting sort by dst ----------------
__global__ void zero_kernel() {
    int i = blockIdx.x * blockDim.x + threadIdx.x;
    if (i < N_NODES_) g_count[i] = 0;
}
__global__ void hist_kernel(const int* __restrict__ edge_index) {
    int e = blockIdx.x * blockDim.x + threadIdx.x;
    if (e < N_EDGES_) atomicAdd(&g_count[edge_index[e]], 1);   // dst = row 0
}
__global__ void scan1_kernel() {
    __shared__ int s[256];
    int tid = threadIdx.x;
    int i = blockIdx.x * 256 + tid;
    int v = (i < N_NODES_) ? g_count[i] : 0;
    s[tid] = v; __syncthreads();
    #pragma unroll
    for (int d = 1; d < 256; d <<= 1) {
        int x = (tid >= d) ? s[tid - d] : 0;
        __syncthreads();
        s[tid] += x;
        __syncthreads();
    }
    if (i < N_NODES_) {
        int o = s[tid] - v;          // exclusive within block
        g_offs[i] = o;
        g_cursor[i] = o;
    }
    if (tid == 255) g_part[blockIdx.x] = s[255];
}
__global__ void scan2_kernel() {
    __shared__ int s[128];
    int tid = threadIdx.x;
    int v = (tid < SCAN_BLKS_) ? g_part[tid] : 0;
    s[tid] = v; __syncthreads();
    #pragma unroll
    for (int d = 1; d < 128; d <<= 1) {
        int x = (tid >= d) ? s[tid - d] : 0;
        __syncthreads();
        s[tid] += x;
        __syncthreads();
    }
    if (tid < SCAN_BLKS_) g_part[tid] = s[tid] - v;    // exclusive
}
// perm with scan3 folded in: global offset = local cursor + part[block]
__global__ void perm_kernel(const int* __restrict__ edge_index) {
    int e = blockIdx.x * blockDim.x + threadIdx.x;
    if (e < N_EDGES_) {
        int d = edge_index[e];
        int p = atomicAdd(&g_cursor[d], 1) + g_part[d >> 8];
        g_perm[p] = e;
    }
}

// ---------------------------------------------------------------------------
// SGEMM 128x64 tile, 8x4 microtile, BK=16.
// Per k: 2 LDS.128 (A) + 1 LDS.128 (B) -> 32 FMA.
// ---------------------------------------------------------------------------
template <bool DO_SILU>
__global__ __launch_bounds__(256) void sgemm_bias(
    const float* __restrict__ A, const float* __restrict__ B,
    const float* __restrict__ bias, float* __restrict__ C,
    int M, int N, int K) {
    __shared__ __align__(16) float As[16][136];   // pad 8: 16B-aligned rows
    __shared__ __align__(16) float Bs[16][64];
    const int bm = blockIdx.y * 128;
    const int bn = blockIdx.x * 64;
    const int tid = threadIdx.x;
    const int tx = tid & 15;       // col group (4 cols)
    const int ty = tid >> 4;       // row group (8 rows)

    float acc[8][4] = {};

    for (int k0 = 0; k0 < K; k0 += 16) {
        #pragma unroll
        for (int i = 0; i < 8; i++) {
            int idx = tid + 256 * i;          // 0..2047
            int m = idx >> 4, k = idx & 15;
            int gm = bm + m;
            As[k][m] = (gm < M) ? A[(size_t)gm * K + k0 + k] : 0.0f;
        }
        #pragma unroll
        for (int i = 0; i < 4; i++) {
            int idx = tid + 256 * i;          // 0..1023
            int k = idx >> 6, n = idx & 63;
            Bs[k][n] = B[(size_t)(k0 + k) * N + bn + n];
        }
        __syncthreads();
        #pragma unroll
        for (int k = 0; k < 16; k++) {
            float4 a0 = *reinterpret_cast<const float4*>(&As[k][ty * 8]);
            float4 a1 = *reinterpret_cast<const float4*>(&As[k][ty * 8 + 4]);
            float4 bq = *reinterpret_cast<const float4*>(&Bs[k][tx * 4]);
            float a[8] = {a0.x, a0.y, a0.z, a0.w, a1.x, a1.y, a1.z, a1.w};
            float b[4] = {bq.x, bq.y, bq.z, bq.w};
            #pragma unroll
            for (int i = 0; i < 8; i++)
                #pragma unroll
                for (int j = 0; j < 4; j++)
                    acc[i][j] = fmaf(a[i], b[j], acc[i][j]);
        }
        __syncthreads();
    }

    #pragma unroll
    for (int i = 0; i < 8; i++) {
        int m = bm + ty * 8 + i;
        if (m >= M) continue;
        #pragma unroll
        for (int j = 0; j < 4; j++) {
            int n = bn + tx * 4 + j;
            float v = acc[i][j] + bias[n];
            if (DO_SILU) v = v / (1.0f + expf(-v));
            C[(size_t)m * N + n] = v;
        }
    }
}

// ---------------------------------------------------------------------------
// Persistent node kernel with cross-batch software pipelining.
// grid=148, 576 threads; thread t owns filter column t.
// Gathers for batch b+1 are issued (into ping-pong regs) before computing
// batch b, hiding LDG latency behind a full batch of FMA work + barrier.
// ---------------------------------------------------------------------------
__device__ __forceinline__ int irrep_of(int k) {
    if (k < 128) return k;
    if (k < 320) return 128 + (k - 128) / 3;
    return 192 + (k - 320) / 5;
}

__global__ __launch_bounds__(576, 1) void node_kernel(
    const float* __restrict__ rbf, const float* __restrict__ fcut,
    const float* __restrict__ rsh, const int* __restrict__ edge_index,
    const float* __restrict__ Wrbf, const float* __restrict__ brbf,
    const float* __restrict__ x_scalar, const float* __restrict__ x_sph,
    float* __restrict__ out_scalar, float* __restrict__ out_sph) {
    const float* __restrict__ scalar_out = g_scalar_out;

    __shared__ __align__(16) float rbf_s[MAXD_][24];
    __shared__ int   eid_s[MAXD_];
    __shared__ int   src_s[MAXD_];
    __shared__ float fc_s[MAXD_];
    __shared__ float gate_s[2][EPB_][2 * NUM_IRREPS_];

    const int t = threadIdx.x;

    float w[NUM_BASIS_];
    #pragma unroll
    for (int k = 0; k < NUM_BASIS_; k++) w[k] = Wrbf[k * HIDDEN_ + t];
    const float bb = brbf[t];
    const int ir = (t < SPH_DIM_) ? irrep_of(t) : 0;
    const bool is_sph = (t < SPH_DIM_);

    int pp = 0;

// issue all gathers for the batch starting at meta slot `base`
#define PREFETCH(base, sv, xv, rv)                                          \
    {                                                                       \
        _Pragma("unroll")                                                   \
        for (int e = 0; e < EPB_; e++) {                                    \
            int s_ = src_s[(base) + e];                                     \
            sv[e] = __ldg(&scalar_out[(size_t)s_ * HIDDEN_ + t]);           \
        }                                                                   \
        if (is_sph) {                                                       \
            _Pragma("unroll")                                               \
            for (int e = 0; e < EPB_; e++) {                                \
                int s_ = src_s[(base) + e];                                 \
                int q_ = eid_s[(base) + e];                                 \
                xv[e] = __ldg(&x_sph[(size_t)s_ * SPH_DIM_ + t]);           \
                rv[e] = __ldcs(&rsh[(size_t)q_ * SPH_DIM_ + t]);            \
            }                                                               \
        }                                                                   \
    }

// filter + gating + barrier + message accumulate for batch at `base`
#define COMPUTE(base, sv, xv, rv)                                           \
    {                                                                       \
        float a_[EPB_];                                                     \
        _Pragma("unroll")                                                   \
        for (int e = 0; e < EPB_; e++) {                                    \
            const float4* rp =                                              \
                reinterpret_cast<const float4*>(&rbf_s[(base) + e][0]);     \
            float4 q0 = rp[0], q1 = rp[1], q2 = rp[2], q3 = rp[3],          \
                   q4 = rp[4];                                              \
            float v = bb;                                                   \
            v = fmaf(q0.x, w[0],  v); v = fmaf(q0.y, w[1],  v);             \
            v = fmaf(q0.z, w[2],  v); v = fmaf(q0.w, w[3],  v);             \
            v = fmaf(q1.x, w[4],  v); v = fmaf(q1.y, w[5],  v);             \
            v = fmaf(q1.z, w[6],  v); v = fmaf(q1.w, w[7],  v);             \
            v = fmaf(q2.x, w[8],  v); v = fmaf(q2.y, w[9],  v);             \
            v = fmaf(q2.z, w[10], v); v = fmaf(q2.w, w[11], v);             \
            v = fmaf(q3.x, w[12], v); v = fmaf(q3.y, w[13], v);             \
            v = fmaf(q3.z, w[14], v); v = fmaf(q3.w, w[15], v);             \
            v = fmaf(q4.x, w[16], v); v = fmaf(q4.y, w[17], v);             \
            v = fmaf(q4.z, w[18], v); v = fmaf(q4.w, w[19], v);             \
            a_[e] = v * fc_s[(base) + e];                                   \
        }                                                                   \
        _Pragma("unroll")                                                   \
        for (int e = 0; e < EPB_; e++) a_[e] *= sv[e];                      \
        if (t < 2 * NUM_IRREPS_) {                                          \
            _Pragma("unroll")                                               \
            for (int e = 0; e < EPB_; e++) gate_s[pp][e][t] = a_[e];        \
        } else {                                                            \
            _Pragma("unroll")                                               \
            for (int e = 0; e < EPB_; e++) acc_sc += a_[e];                 \
        }                                                                   \
        __syncthreads();                                                    \
        if (is_sph) {                                                       \
            _Pragma("unroll")                                               \
            for (int e = 0; e < EPB_; e++) {                                \
                acc_sph = fmaf(xv[e], gate_s[pp][e][ir], acc_sph);          \
                acc_sph = fmaf(rv[e], gate_s[pp][e][NUM_IRREPS_ + ir],      \
                               acc_sph);                                    \
            }                                                               \
        }                                                                   \
        pp ^= 1;                                                            \
    }

    for (int n = blockIdx.x; n < N_NODES_; n += gridDim.x) {
        const int off = g_offs[n] + g_part[n >> 8];
        const int deg = g_count[n];

        float acc_sph = 0.0f;
        float acc_sc  = 0.0f;

        for (int c0 = 0; c0 < deg; c0 += MAXD_) {
            const int cnt = min(MAXD_, deg - c0);

            // ---- chunk metadata (pad with edge j=0, fc=0) ----
            if (t < MAXD_) {
                int j = (t < cnt) ? t : 0;
                int eid = __ldg(&g_perm[off + c0 + j]);
                eid_s[t] = eid;
                src_s[t] = __ldg(&edge_index[N_EDGES_ + eid]);
                fc_s[t]  = (t < cnt) ? __ldg(&fcut[eid]) : 0.0f;
            }
            for (int i = t; i < MAXD_ * NUM_BASIS_; i += 576) {
                int e = i / NUM_BASIS_, k = i % NUM_BASIS_;
                int j = (e < cnt) ? e : 0;
                int eid = __ldg(&g_perm[off + c0 + j]);
                rbf_s[e][k] = __ldg(&rbf[(size_t)eid * NUM_BASIS_ + k]);
            }
            __syncthreads();

            const int nb = (cnt + EPB_ - 1) / EPB_;   // 1..4
            float sA[EPB_], xA[EPB_], rA[EPB_];
            float sB[EPB_], xB[EPB_], rB[EPB_];

            PREFETCH(0, sA, xA, rA);
            for (int b = 0; b < nb; b += 2) {
                if (b + 1 < nb) PREFETCH((b + 1) * EPB_, sB, xB, rB);
                COMPUTE(b * EPB_, sA, xA, rA);
                if (b + 1 < nb) {
                    if (b + 2 < nb) PREFETCH((b + 2) * EPB_, sA, xA, rA);
                    COMPUTE((b + 1) * EPB_, sB, xB, rB);
                }
            }
        }

        // residual + single write (covers deg==0 nodes too)
        if (is_sph)
            out_sph[(size_t)n * SPH_DIM_ + t] =
                x_sph[(size_t)n * SPH_DIM_ + t] + acc_sph;
        if (t >= 2 * NUM_IRREPS_) {
            int c = t - 2 * NUM_IRREPS_;
            out_scalar[(size_t)n * NODE_DIM_ + c] =
                x_scalar[(size_t)n * NODE_DIM_ + c] + acc_sc;
        }
    }
#undef PREFETCH
#undef COMPUTE
}

// ---------------------------------------------------------------------------
extern "C" void kernel_launch(void* const* d_in, const int* in_sizes, int n_in,
                              void* d_out, int out_size) {
    const float* x_scalar = (const float*)d_in[0];
    const float* x_sph    = (const float*)d_in[1];
    const float* rbf      = (const float*)d_in[2];
    const float* fcut     = (const float*)d_in[3];
    const float* rsh      = (const float*)d_in[4];
    const int*   eidx     = (const int*)d_in[5];
    const float* W1       = (const float*)d_in[6];
    const float* b1       = (const float*)d_in[7];
    const float* W2       = (const float*)d_in[8];
    const float* b2       = (const float*)d_in[9];
    const float* Wrbf     = (const float*)d_in[10];
    const float* brbf     = (const float*)d_in[11];

    float* out        = (float*)d_out;
    float* out_scalar = out;
    float* out_sph    = out + (size_t)N_NODES_ * NODE_DIM_;

    float* hidden = nullptr;
    float* so     = nullptr;
    cudaGetSymbolAddress((void**)&hidden, g_hidden);
    cudaGetSymbolAddress((void**)&so, g_scalar_out);

    zero_kernel<<<SCAN_BLKS_, 256>>>();                                      // 0
    hist_kernel<<<(N_EDGES_ + 255) / 256, 256>>>(eidx);                      // 1
    {
        dim3 grid(NODE_DIM_ / 64, (N_NODES_ + 127) / 128);
        sgemm_bias<true><<<grid, 256>>>(x_scalar, W1, b1, hidden,
                                        N_NODES_, NODE_DIM_, NODE_DIM_);     // 2
    }
    {
        dim3 grid(HIDDEN_ / 64, (N_NODES_ + 127) / 128);
        sgemm_bias<false><<<grid, 256>>>(hidden, W2, b2, so,
                                         N_NODES_, HIDDEN_, NODE_DIM_);      // 3
    }
    scan1_kernel<<<SCAN_BLKS_, 256>>>();                                     // 4
    scan2_kernel<<<1, 128>>>();                                              // 5
    perm_kernel<<<(N_EDGES_ + 255) / 256, 256>>>(eidx);                      // 6

    node_kernel<<<148, 576>>>(rbf, fcut, rsh, eidx, Wrbf, brbf,
                              x_scalar, x_sph, out_scalar, out_sph);         // 7
}

// round 8
// speedup vs baseline: 1.6319x; 1.6319x over previous
#include <cuda_runtime.h>
#include <cstdint>
#include <math.h>

#define NODE_DIM_   128
#define NUM_IRREPS_ 224
#define SPH_DIM_    480
#define HIDDEN_     576
#define NUM_BASIS_  20
#define N_NODES_    30000
#define N_EDGES_    480000
#define EPB_        8
#define MAXD_       32

// Scratch (device globals)
__device__ float g_hidden[(size_t)N_NODES_ * NODE_DIM_];
__device__ float g_scalar_out[(size_t)N_NODES_ * HIDDEN_];
__device__ int   g_count[N_NODES_];          // zero-init at load; re-zeroed by scan_all
__device__ int   g_offs[N_NODES_ + 1];
__device__ int   g_cursor[N_NODES_];
__device__ int   g_perm[N_EDGES_];

// ---------------- packed f32x2 helpers ----------------
__device__ __forceinline__ unsigned long long pack2(float lo, float hi) {
    unsigned long long r;
    asm("mov.b64 %0, {%1, %2};" : "=l"(r) : "f"(lo), "f"(hi));
    return r;
}
__device__ __forceinline__ float2 unpack2(unsigned long long v) {
    float2 f;
    asm("mov.b64 {%0, %1}, %2;" : "=f"(f.x), "=f"(f.y) : "l"(v));
    return f;
}
#define FFMA2(acc, r, w) \
    asm("fma.rn.f32x2 %0, %1, %2, %0;" : "+l"(acc) : "l"(r), "l"(w))

// ---------------- counting sort by dst ----------------
__global__ void hist_kernel(const int* __restrict__ edge_index) {
    int e = blockIdx.x * blockDim.x + threadIdx.x;
    if (e < N_EDGES_) atomicAdd(&g_count[edge_index[e]], 1);   // dst = row 0
}

// single-block scan of g_count -> g_offs/g_cursor; zeroes g_count for next call
__global__ __launch_bounds__(1024) void scan_all() {
    __shared__ int s[1024];
    const int C = 30;                      // 1024*30 >= 30000
    const int t = threadIdx.x;
    const int base = t * C;
    int local[C];
    int sum = 0;
    #pragma unroll
    for (int j = 0; j < C; j++) {
        int i = base + j;
        int v = (i < N_NODES_) ? g_count[i] : 0;
        local[j] = sum;                    // thread-local exclusive
        sum += v;
    }
    s[t] = sum;
    __syncthreads();
    #pragma unroll
    for (int d = 1; d < 1024; d <<= 1) {   // Hillis-Steele inclusive
        int x = (t >= d) ? s[t - d] : 0;
        __syncthreads();
        s[t] += x;
        __syncthreads();
    }
    int pre = (t > 0) ? s[t - 1] : 0;      // exclusive over threads
    #pragma unroll
    for (int j = 0; j < C; j++) {
        int i = base + j;
        if (i < N_NODES_) {
            int o = pre + local[j];
            g_offs[i] = o;
            g_cursor[i] = o;
            g_count[i] = 0;                // ready for next replay's hist
        }
    }
    if (t == 1023) g_offs[N_NODES_] = s[1023];
}

__global__ void perm_kernel(const int* __restrict__ edge_index) {
    int e = blockIdx.x * blockDim.x + threadIdx.x;
    if (e < N_EDGES_) {
        int d = edge_index[e];
        int p = atomicAdd(&g_cursor[d], 1);
        g_perm[p] = e;
    }
}

// ---------------------------------------------------------------------------
// SGEMM 64x64, 4x4 microtile, contiguous fragments: per k 2 LDS.128 -> 16 FMA
// ---------------------------------------------------------------------------
template <bool DO_SILU>
__global__ __launch_bounds__(256) void sgemm_bias(
    const float* __restrict__ A, const float* __restrict__ B,
    const float* __restrict__ bias, float* __restrict__ C,
    int M, int N, int K) {
    __shared__ __align__(16) float As[16][68];   // 68*4=272B rows, 16B aligned
    __shared__ __align__(16) float Bs[16][64];
    const int bm = blockIdx.y * 64;
    const int bn = blockIdx.x * 64;
    const int tid = threadIdx.x;
    const int tx = tid & 15;       // col group: 4 contiguous cols
    const int ty = tid >> 4;       // row group: 4 contiguous rows

    float acc[4][4] = {};

    for (int k0 = 0; k0 < K; k0 += 16) {
        #pragma unroll
        for (int i = 0; i < 4; i++) {
            int idx = tid + 256 * i;          // 0..1023
            int m = idx >> 4, k = idx & 15;   // consecutive tid -> consecutive k
            int gm = bm + m;
            As[k][m] = (gm < M) ? A[(size_t)gm * K + k0 + k] : 0.0f;
        }
        #pragma unroll
        for (int i = 0; i < 4; i++) {
            int idx = tid + 256 * i;
            int k = idx >> 6, n = idx & 63;
            Bs[k][n] = B[(size_t)(k0 + k) * N + bn + n];
        }
        __syncthreads();
        #pragma unroll
        for (int k = 0; k < 16; k++) {
            float4 aq = *reinterpret_cast<const float4*>(&As[k][ty * 4]);
            float4 bq = *reinterpret_cast<const float4*>(&Bs[k][tx * 4]);
            float a[4] = {aq.x, aq.y, aq.z, aq.w};
            float b[4] = {bq.x, bq.y, bq.z, bq.w};
            #pragma unroll
            for (int i = 0; i < 4; i++)
                #pragma unroll
                for (int j = 0; j < 4; j++)
                    acc[i][j] = fmaf(a[i], b[j], acc[i][j]);
        }
        __syncthreads();
    }

    float4 bq = *reinterpret_cast<const float4*>(&bias[bn + tx * 4]);
    float bv[4] = {bq.x, bq.y, bq.z, bq.w};
    #pragma unroll
    for (int i = 0; i < 4; i++) {
        int m = bm + ty * 4 + i;
        if (m >= M) continue;
        float4 o;
        float* op = &o.x;
        #pragma unroll
        for (int j = 0; j < 4; j++) {
            float v = acc[i][j] + bv[j];
            if (DO_SILU) v = v / (1.0f + expf(-v));
            op[j] = v;
        }
        *reinterpret_cast<float4*>(&C[(size_t)m * N + bn + tx * 4]) = o;
    }
}

// ---------------------------------------------------------------------------
// Persistent node kernel; thread t owns filter column t.
// Filter dots use packed f32x2 FMA over edge pairs (2j, 2j+1); rbf stored
// pre-paired in smem (float2), weights pre-packed {w,w} in registers.
// ---------------------------------------------------------------------------
__device__ __forceinline__ int irrep_of(int k) {
    if (k < 128) return k;
    if (k < 320) return 128 + (k - 128) / 3;
    return 192 + (k - 320) / 5;
}

__global__ __launch_bounds__(576, 1) void node_kernel(
    const float* __restrict__ rbf, const float* __restrict__ fcut,
    const float* __restrict__ rsh, const int* __restrict__ edge_index,
    const float* __restrict__ Wrbf, const float* __restrict__ brbf,
    const float* __restrict__ x_scalar, const float* __restrict__ x_sph,
    float* __restrict__ out_scalar, float* __restrict__ out_sph) {
    const float* __restrict__ scalar_out = g_scalar_out;

    __shared__ __align__(8) float2 rbf_p[MAXD_ / 2][NUM_BASIS_]; // lanes=edge pair
    __shared__ int   eid_s[MAXD_];
    __shared__ int   src_s[MAXD_];
    __shared__ float fc_s[MAXD_];
    __shared__ float gate_s[2][EPB_][2 * NUM_IRREPS_];

    const int t = threadIdx.x;

    // packed weights {w,w} for this column
    unsigned long long wp[NUM_BASIS_];
    #pragma unroll
    for (int k = 0; k < NUM_BASIS_; k++) {
        float wv = Wrbf[k * HIDDEN_ + t];
        wp[k] = pack2(wv, wv);
    }
    const unsigned long long bbp = pack2(brbf[t], brbf[t]);
    const int ir = (t < SPH_DIM_) ? irrep_of(t) : 0;
    const bool is_sph = (t < SPH_DIM_);

    // clear rbf_p so padded lanes are finite (fc=0 kills their contribution)
    for (int i = t; i < (MAXD_ / 2) * NUM_BASIS_ * 2; i += 576)
        reinterpret_cast<float*>(rbf_p)[i] = 0.0f;

    int pp = 0;

    for (int n = blockIdx.x; n < N_NODES_; n += gridDim.x) {
        const int off = g_offs[n];
        const int deg = g_offs[n + 1] - off;

        float acc_sph = 0.0f;
        float acc_sc  = 0.0f;

        for (int c0 = 0; c0 < deg; c0 += MAXD_) {
            const int cnt = min(MAXD_, deg - c0);

            // ---- chunk metadata (pad with edge j=0, fc=0) ----
            if (t < MAXD_) {
                int j = (t < cnt) ? t : 0;
                int eid = __ldg(&g_perm[off + c0 + j]);
                eid_s[t] = eid;
                src_s[t] = __ldg(&edge_index[N_EDGES_ + eid]);
                fc_s[t]  = (t < cnt) ? __ldg(&fcut[eid]) : 0.0f;
            }
            for (int i = t; i < cnt * NUM_BASIS_; i += 576) {
                int e = i / NUM_BASIS_, k = i % NUM_BASIS_;
                int eid = __ldg(&g_perm[off + c0 + e]);     // L1 broadcast
                float v = __ldg(&rbf[(size_t)eid * NUM_BASIS_ + k]);
                reinterpret_cast<float*>(&rbf_p[e >> 1][k])[e & 1] = v;
            }
            __syncthreads();

            const int nb = (cnt + EPB_ - 1) / EPB_;   // 1..4
            for (int b = 0; b < nb; b++) {
                const int base = b * EPB_;

                // gathers issued first (reads of meta smem are pre-barrier: safe)
                float s[EPB_];
                #pragma unroll
                for (int e = 0; e < EPB_; e++)
                    s[e] = __ldg(&scalar_out[(size_t)src_s[base + e] * HIDDEN_ + t]);

                float xv[EPB_], rv[EPB_];
                if (is_sph) {
                    #pragma unroll
                    for (int e = 0; e < EPB_; e++) {
                        xv[e] = __ldg(&x_sph[(size_t)src_s[base + e] * SPH_DIM_ + t]);
                        rv[e] = __ldcs(&rsh[(size_t)eid_s[base + e] * SPH_DIM_ + t]);
                    }
                }

                // filter dots: packed pairs of edges, f32x2 FMA
                float a[EPB_];
                #pragma unroll
                for (int j = 0; j < EPB_ / 2; j++) {
                    unsigned long long acc = bbp;
                    const unsigned long long* rp =
                        reinterpret_cast<const unsigned long long*>(
                            &rbf_p[(base >> 1) + j][0]);
                    #pragma unroll
                    for (int k = 0; k < NUM_BASIS_; k++)
                        FFMA2(acc, rp[k], wp[k]);
                    float2 u = unpack2(acc);
                    a[2 * j]     = u.x;
                    a[2 * j + 1] = u.y;
                }

                #pragma unroll
                for (int e = 0; e < EPB_; e++)
                    s[e] = s[e] * (a[e] * fc_s[base + e]);

                if (t < 2 * NUM_IRREPS_) {
                    #pragma unroll
                    for (int e = 0; e < EPB_; e++) gate_s[pp][e][t] = s[e];
                } else {
                    #pragma unroll
                    for (int e = 0; e < EPB_; e++) acc_sc += s[e];
                }
                __syncthreads();   // gates ready; gathers land during wait

                if (is_sph) {
                    #pragma unroll
                    for (int e = 0; e < EPB_; e++) {
                        acc_sph = fmaf(xv[e], gate_s[pp][e][ir], acc_sph);
                        acc_sph = fmaf(rv[e], gate_s[pp][e][NUM_IRREPS_ + ir],
                                       acc_sph);
                    }
                }
                pp ^= 1;
            }
        }

        // residual + single write (covers deg==0 too)
        if (is_sph)
            out_sph[(size_t)n * SPH_DIM_ + t] =
                x_sph[(size_t)n * SPH_DIM_ + t] + acc_sph;
        if (t >= 2 * NUM_IRREPS_) {
            int c = t - 2 * NUM_IRREPS_;
            out_scalar[(size_t)n * NODE_DIM_ + c] =
                x_scalar[(size_t)n * NODE_DIM_ + c] + acc_sc;
        }
    }
}

// ---------------------------------------------------------------------------
extern "C" void kernel_launch(void* const* d_in, const int* in_sizes, int n_in,
                              void* d_out, int out_size) {
    const float* x_scalar = (const float*)d_in[0];
    const float* x_sph    = (const float*)d_in[1];
    const float* rbf      = (const float*)d_in[2];
    const float* fcut     = (const float*)d_in[3];
    const float* rsh      = (const float*)d_in[4];
    const int*   eidx     = (const int*)d_in[5];
    const float* W1       = (const float*)d_in[6];
    const float* b1       = (const float*)d_in[7];
    const float* W2       = (const float*)d_in[8];
    const float* b2       = (const float*)d_in[9];
    const float* Wrbf     = (const float*)d_in[10];
    const float* brbf     = (const float*)d_in[11];

    float* out        = (float*)d_out;
    float* out_scalar = out;
    float* out_sph    = out + (size_t)N_NODES_ * NODE_DIM_;

    float* hidden = nullptr;
    float* so     = nullptr;
    cudaGetSymbolAddress((void**)&hidden, g_hidden);
    cudaGetSymbolAddress((void**)&so, g_scalar_out);

    // g_count is zero at first call (static init) and re-zeroed by scan_all.
    hist_kernel<<<(N_EDGES_ + 255) / 256, 256>>>(eidx);                      // 0
    {
        dim3 grid(NODE_DIM_ / 64, (N_NODES_ + 63) / 64);
        sgemm_bias<true><<<grid, 256>>>(x_scalar, W1, b1, hidden,
                                        N_NODES_, NODE_DIM_, NODE_DIM_);     // 1
    }
    scan_all<<<1, 1024>>>();                                                 // 2
    {
        dim3 grid(HIDDEN_ / 64, (N_NODES_ + 63) / 64);
        sgemm_bias<false><<<grid, 256>>>(hidden, W2, b2, so,
                                         N_NODES_, HIDDEN_, NODE_DIM_);      // 3
    }
    perm_kernel<<<(N_EDGES_ + 255) / 256, 256>>>(eidx);                      // 4

    node_kernel<<<148, 576>>>(rbf, fcut, rsh, eidx, Wrbf, brbf,
                              x_scalar, x_sph, out_scalar, out_sph);         // 5
}